// round 5
// baseline (speedup 1.0000x reference)
#include <cuda_runtime.h>
#include <math.h>
#include <stdint.h>

// ---------------------------------------------------------------------------
// Problem constants
// ---------------------------------------------------------------------------
namespace cfg {
constexpr int B = 4, S = 64, D = 512, H = 8, DH = 64, DFF = 2048, L = 2;
constexpr int V = 32128, T = 16;
constexpr int NTOK = B * S;          // 256 encoder tokens
constexpr float NEG = -1e9f;
constexpr float EPS = 1e-6f;
constexpr float SCALE = 0.125f;      // 1/sqrt(DH)
constexpr int YCH = 32;              // chunks for probs@emb (V = 32*1004)
constexpr int CH = V / YCH;          // 1004
}
using namespace cfg;

// ---------------------------------------------------------------------------
// Scratch (single __device__ buffer, offsets in floats)
// ---------------------------------------------------------------------------
constexpr size_t OFF_X    = 0;
constexpr size_t OFF_H    = OFF_X   + (size_t)NTOK * D;
constexpr size_t OFF_Q    = OFF_H   + (size_t)NTOK * D;
constexpr size_t OFF_K    = OFF_Q   + (size_t)NTOK * D;
constexpr size_t OFF_V    = OFF_K   + (size_t)NTOK * D;
constexpr size_t OFF_AO   = OFF_V   + (size_t)NTOK * D;
constexpr size_t OFF_FF   = OFF_AO  + (size_t)NTOK * D;
constexpr size_t OFF_HS   = OFF_FF  + (size_t)NTOK * DFF;
constexpr size_t OFF_KC   = OFF_HS  + (size_t)NTOK * D;        // cross K cache [L][NTOK][D]
constexpr size_t OFF_VC   = OFF_KC  + (size_t)L * NTOK * D;    // cross V cache
constexpr size_t OFF_KS   = OFF_VC  + (size_t)L * NTOK * D;    // self K cache [L][B][T][D]
constexpr size_t OFF_VS   = OFF_KS  + (size_t)L * B * T * D;
constexpr size_t OFF_XD   = OFF_VS  + (size_t)L * B * T * D;   // decoder x [B][D]
constexpr size_t OFF_QD   = OFF_XD  + (size_t)B * D;
constexpr size_t OFF_KD   = OFF_QD  + (size_t)B * D;
constexpr size_t OFF_VD   = OFF_KD  + (size_t)B * D;
constexpr size_t OFF_AD   = OFF_VD  + (size_t)B * D;
constexpr size_t OFF_FFD  = OFF_AD  + (size_t)B * D;
constexpr size_t OFF_LOG  = OFF_FFD + (size_t)B * DFF;
constexpr size_t OFF_YP   = OFF_LOG + (size_t)B * V;           // [YCH][B][D] partials
constexpr size_t OFF_BIAS = OFF_YP  + (size_t)YCH * B * D;
constexpr size_t TOTALF   = OFF_BIAS + (size_t)B * S;

__device__ __align__(16) float g_buf[TOTALF];

// ---------------------------------------------------------------------------
// Kernels
// ---------------------------------------------------------------------------

// Encoder input embedding + enc_bias from attention_mask.
__global__ void k_embed(const int* __restrict__ ids, const float* __restrict__ mask,
                        const float* __restrict__ emb, float* __restrict__ x,
                        float* __restrict__ bias)
{
    int tok = blockIdx.x;                 // 0..255
    int tid = threadIdx.x;                // 256
    int id = ids[tok];
    const float* e = emb + (size_t)id * D;
    x[(size_t)tok * D + tid]       = e[tid];
    x[(size_t)tok * D + 256 + tid] = e[256 + tid];
    if (tid == 0) bias[tok] = (1.0f - mask[tok]) * NEG;
}

// Decoder initial token: pad embedding (row 0) broadcast to B rows.
__global__ void k_padinit(const float* __restrict__ emb, float* __restrict__ xd)
{
    int b = blockIdx.x, tid = threadIdx.x;  // 256
    xd[(size_t)b * D + tid]       = emb[tid];
    xd[(size_t)b * D + 256 + tid] = emb[256 + tid];
}

// RMSNorm, width D=512, one block per row, 256 threads.
__global__ void k_rmsnorm(const float* __restrict__ x, const float* __restrict__ w,
                          float* __restrict__ y)
{
    int r = blockIdx.x, tid = threadIdx.x;
    __shared__ float red[256];
    float v0 = x[(size_t)r * D + tid];
    float v1 = x[(size_t)r * D + 256 + tid];
    red[tid] = v0 * v0 + v1 * v1;
    __syncthreads();
    for (int s = 128; s > 0; s >>= 1) {
        if (tid < s) red[tid] += red[tid + s];
        __syncthreads();
    }
    float sc = rsqrtf(red[0] * (1.0f / D) + EPS);
    y[(size_t)r * D + tid]       = v0 * sc * w[tid];
    y[(size_t)r * D + 256 + tid] = v1 * sc * w[256 + tid];
}

// Tiled SGEMM: C = A[M,K] @ W[K,N] (+Res) (+relu). 64x64 tile, 256 threads,
// blockIdx.z picks among up to 3 (W,C) pairs (fused QKV / fused cross-KV).
__global__ void k_sgemm(const float* __restrict__ A,
                        const float* __restrict__ W0, const float* __restrict__ W1,
                        const float* __restrict__ W2,
                        const float* __restrict__ Res,
                        float* __restrict__ C0, float* __restrict__ C1, float* __restrict__ C2,
                        int N, int K, int relu)
{
    const float* W = (blockIdx.z == 0) ? W0 : (blockIdx.z == 1) ? W1 : W2;
    float* C       = (blockIdx.z == 0) ? C0 : (blockIdx.z == 1) ? C1 : C2;
    __shared__ float As[64 * 16];
    __shared__ float Bs[16 * 64];
    int tid = threadIdx.x;
    int tx = tid & 15, ty = tid >> 4;
    int bm = blockIdx.y * 64, bn = blockIdx.x * 64;
    float acc[4][4] = {};
    for (int k0 = 0; k0 < K; k0 += 16) {
        {   // A tile 64x16 (float4)
            int r = tid >> 2, c = (tid & 3) << 2;
            *(float4*)&As[r * 16 + c] = *(const float4*)&A[(size_t)(bm + r) * K + k0 + c];
        }
        {   // B tile 16x64 (float4, coalesced)
            int r = tid >> 4, c = (tid & 15) << 2;
            *(float4*)&Bs[r * 64 + c] = *(const float4*)&W[(size_t)(k0 + r) * N + bn + c];
        }
        __syncthreads();
        #pragma unroll
        for (int k = 0; k < 16; k++) {
            float am[4], bv[4];
            #pragma unroll
            for (int i = 0; i < 4; i++) am[i] = As[(ty * 4 + i) * 16 + k];
            #pragma unroll
            for (int j = 0; j < 4; j++) bv[j] = Bs[k * 64 + tx * 4 + j];
            #pragma unroll
            for (int i = 0; i < 4; i++)
                #pragma unroll
                for (int j = 0; j < 4; j++) acc[i][j] += am[i] * bv[j];
        }
        __syncthreads();
    }
    #pragma unroll
    for (int i = 0; i < 4; i++) {
        int row = bm + ty * 4 + i;
        #pragma unroll
        for (int j = 0; j < 4; j++) {
            int col = bn + tx * 4 + j;
            float v = acc[i][j];
            if (Res) v += Res[(size_t)row * N + col];
            if (relu) v = fmaxf(v, 0.0f);
            C[(size_t)row * N + col] = v;
        }
    }
}

// Encoder full self-attention. One block per (b,h), 256 threads.
__global__ void k_enc_attn(const float* __restrict__ q, const float* __restrict__ k,
                           const float* __restrict__ v, const float* __restrict__ bias,
                           float* __restrict__ out)
{
    int bh = blockIdx.x, b = bh >> 3, h = bh & 7;
    int tid = threadIdx.x;
    __shared__ float sc[64 * 64];
    for (int i = tid; i < 4096; i += 256) {
        int qi = i >> 6, ki = i & 63;
        const float* qp = &q[(size_t)(b * S + qi) * D + h * DH];
        const float* kp = &k[(size_t)(b * S + ki) * D + h * DH];
        float s = 0.f;
        #pragma unroll 8
        for (int e = 0; e < DH; e++) s += qp[e] * kp[e];
        sc[i] = s * SCALE + bias[b * S + ki];
    }
    __syncthreads();
    if (tid < 64) {   // softmax over each score row
        float* row = &sc[tid * 64];
        float m = -1e30f;
        for (int j = 0; j < 64; j++) m = fmaxf(m, row[j]);
        float ss = 0.f;
        for (int j = 0; j < 64; j++) { row[j] = expf(row[j] - m); ss += row[j]; }
        float inv = 1.0f / ss;
        for (int j = 0; j < 64; j++) row[j] *= inv;
    }
    __syncthreads();
    for (int i = tid; i < 4096; i += 256) {
        int qi = i >> 6, dd = i & 63;
        float o = 0.f;
        #pragma unroll 8
        for (int j = 0; j < 64; j++)
            o += sc[qi * 64 + j] * v[(size_t)(b * S + j) * D + h * DH + dd];
        out[(size_t)(b * S + qi) * D + h * DH + dd] = o;
    }
}

// Small-M GEMM (M=B=4) with optional fused RMSNorm on the input, optional
// residual and relu. 128 threads; grid (N/128, nmat); blockIdx.y picks W/C.
__global__ void k_vgemm(const float* __restrict__ X, const float* __restrict__ LN,
                        const float* __restrict__ W0, const float* __restrict__ W1,
                        const float* __restrict__ W2,
                        const float* __restrict__ Res,
                        float* __restrict__ C0, float* __restrict__ C1, float* __restrict__ C2,
                        int K, int N, int relu)
{
    const float* W = (blockIdx.y == 0) ? W0 : (blockIdx.y == 1) ? W1 : W2;
    float* C       = (blockIdx.y == 0) ? C0 : (blockIdx.y == 1) ? C1 : C2;
    __shared__ float a_sh[4 * 2048];
    __shared__ float red[128];
    int tid = threadIdx.x;

    if (LN) {
        for (int r = 0; r < 4; r++) {
            float p = 0.f;
            for (int j = tid; j < K; j += 128) {
                float vv = X[(size_t)r * K + j];
                a_sh[r * K + j] = vv;
                p += vv * vv;
            }
            red[tid] = p;
            __syncthreads();
            for (int s = 64; s > 0; s >>= 1) {
                if (tid < s) red[tid] += red[tid + s];
                __syncthreads();
            }
            float sc = rsqrtf(red[0] / (float)K + EPS);
            for (int j = tid; j < K; j += 128) a_sh[r * K + j] *= sc * LN[j];
            __syncthreads();
        }
    } else {
        for (int j = tid; j < 4 * K; j += 128) a_sh[j] = X[j];
    }
    __syncthreads();

    int n = blockIdx.x * 128 + tid;
    float acc[4] = {};
    #pragma unroll 8
    for (int k = 0; k < K; k++) {
        float w = W[(size_t)k * N + n];
        #pragma unroll
        for (int r = 0; r < 4; r++) acc[r] += a_sh[r * K + k] * w;
    }
    #pragma unroll
    for (int r = 0; r < 4; r++) {
        float vv = acc[r];
        if (Res) vv += Res[(size_t)r * N + n];
        if (relu) vv = fmaxf(vv, 0.0f);
        C[(size_t)r * N + n] = vv;
    }
}

// Decoder self-attention step: append K/V at position t, attend q over 0..t.
// One block per (b,h), 64 threads.
__global__ void k_dec_self(const float* __restrict__ qd, const float* __restrict__ kd,
                           const float* __restrict__ vd,
                           float* __restrict__ kc, float* __restrict__ vc,
                           float* __restrict__ out, int t)
{
    int bh = blockIdx.x, b = bh >> 3, h = bh & 7;
    int d = threadIdx.x;
    int base = b * D + h * DH + d;
    kc[(size_t)(b * T + t) * D + h * DH + d] = kd[base];
    vc[(size_t)(b * T + t) * D + h * DH + d] = vd[base];
    __shared__ float qs[64];
    __shared__ float at[16];
    qs[d] = qd[base];
    __syncthreads();
    if (d <= t) {
        const float* kp = &kc[(size_t)(b * T + d) * D + h * DH];
        float s = 0.f;
        #pragma unroll 8
        for (int e = 0; e < DH; e++) s += qs[e] * kp[e];
        at[d] = s * SCALE;
    }
    __syncthreads();
    if (d == 0) {
        float m = -1e30f;
        for (int j = 0; j <= t; j++) m = fmaxf(m, at[j]);
        float ss = 0.f;
        for (int j = 0; j <= t; j++) { at[j] = expf(at[j] - m); ss += at[j]; }
        float inv = 1.0f / ss;
        for (int j = 0; j <= t; j++) at[j] *= inv;
    }
    __syncthreads();
    float o = 0.f;
    for (int j = 0; j <= t; j++)
        o += at[j] * vc[(size_t)(b * T + j) * D + h * DH + d];
    out[base] = o;
}

// Decoder cross-attention over the 64 encoder keys (cached). Block per (b,h).
__global__ void k_dec_cross(const float* __restrict__ qd, const float* __restrict__ kc,
                            const float* __restrict__ vc, const float* __restrict__ bias,
                            float* __restrict__ out)
{
    int bh = blockIdx.x, b = bh >> 3, h = bh & 7;
    int d = threadIdx.x;
    __shared__ float qs[64];
    __shared__ float at[64];
    qs[d] = qd[b * D + h * DH + d];
    __syncthreads();
    {
        const float* kp = &kc[(size_t)(b * S + d) * D + h * DH];
        float s = 0.f;
        #pragma unroll 8
        for (int e = 0; e < DH; e++) s += qs[e] * kp[e];
        at[d] = s * SCALE + bias[b * S + d];
    }
    __syncthreads();
    if (d == 0) {
        float m = -1e30f;
        for (int j = 0; j < S; j++) m = fmaxf(m, at[j]);
        float ss = 0.f;
        for (int j = 0; j < S; j++) { at[j] = expf(at[j] - m); ss += at[j]; }
        float inv = 1.0f / ss;
        for (int j = 0; j < S; j++) at[j] *= inv;
    }
    __syncthreads();
    float o = 0.f;
    for (int j = 0; j < S; j++)
        o += at[j] * vc[(size_t)(b * S + j) * D + h * DH + d];
    out[b * D + h * DH + d] = o;
}

// LM head: logits[b,n] = rmsnorm(xd,lnf)[b,:] . Wlm[:,n]. 251 blocks x 128.
__global__ void k_lmhead(const float* __restrict__ X, const float* __restrict__ LN,
                         const float* __restrict__ Wlm, float* __restrict__ logits)
{
    __shared__ float a_sh[4 * 512];
    __shared__ float red[128];
    int tid = threadIdx.x;
    for (int r = 0; r < 4; r++) {
        float p = 0.f;
        for (int j = tid; j < D; j += 128) {
            float vv = X[(size_t)r * D + j];
            a_sh[r * D + j] = vv;
            p += vv * vv;
        }
        red[tid] = p;
        __syncthreads();
        for (int s = 64; s > 0; s >>= 1) {
            if (tid < s) red[tid] += red[tid + s];
            __syncthreads();
        }
        float sc = rsqrtf(red[0] * (1.0f / D) + EPS);
        for (int j = tid; j < D; j += 128) a_sh[r * D + j] *= sc * LN[j];
        __syncthreads();
    }

    int n = blockIdx.x * 128 + tid;
    float acc[4] = {};
    #pragma unroll 8
    for (int d = 0; d < D; d++) {
        float w = Wlm[(size_t)d * V + n];
        #pragma unroll
        for (int r = 0; r < 4; r++) acc[r] += a_sh[r * D + d] * w;
    }
    #pragma unroll
    for (int r = 0; r < 4; r++) logits[(size_t)r * V + n] = acc[r];
}

// Softmax over V with argmax; writes prob_history[b,t,:] and pred flag.
__global__ void k_softmax(const float* __restrict__ logits, float* __restrict__ probs,
                          float* __restrict__ flags, int t)
{
    int b = blockIdx.x, tid = threadIdx.x;   // 256 threads
    __shared__ float sval[256];
    __shared__ int sidx[256];
    const float* lg = logits + (size_t)b * V;
    float m = -1e30f; int mi = 0;
    for (int v = tid; v < V; v += 256) {
        float lv = lg[v];
        if (lv > m) { m = lv; mi = v; }
    }
    sval[tid] = m; sidx[tid] = mi;
    __syncthreads();
    for (int s = 128; s > 0; s >>= 1) {
        if (tid < s) {
            if (sval[tid + s] > sval[tid] ||
                (sval[tid + s] == sval[tid] && sidx[tid + s] < sidx[tid])) {
                sval[tid] = sval[tid + s];
                sidx[tid] = sidx[tid + s];
            }
        }
        __syncthreads();
    }
    float gmax = sval[0];
    int gidx = sidx[0];
    __syncthreads();
    float p = 0.f;
    for (int v = tid; v < V; v += 256) p += expf(lg[v] - gmax);
    sval[tid] = p;
    __syncthreads();
    for (int s = 128; s > 0; s >>= 1) {
        if (tid < s) sval[tid] += sval[tid + s];
        __syncthreads();
    }
    float inv = 1.0f / sval[0];
    float* op = probs + ((size_t)b * T + t) * V;
    for (int v = tid; v < V; v += 256) op[v] = expf(lg[v] - gmax) * inv;
    if (tid == 0 && flags) flags[b * T + t] = (gidx == 0) ? 1.0f : 0.0f;  // PAD_ID == 0
}

// Soft embedding partials: ypart[c][b][:] = sum_{v in chunk c} probs[b,v]*emb[v,:]
__global__ void k_softemb(const float* __restrict__ probs, const float* __restrict__ emb,
                          float* __restrict__ ypart, int t)
{
    int c = blockIdx.x;              // 0..31
    int tid = threadIdx.x;           // 512 (one per d)
    __shared__ float ps[4 * CH];
    for (int i = tid; i < 4 * CH; i += 512) {
        int r = i / CH, vv = i - r * CH;
        ps[i] = probs[((size_t)r * T + t) * V + c * CH + vv];
    }
    __syncthreads();
    float acc[4] = {};
    for (int vv = 0; vv < CH; vv++) {
        float e = emb[(size_t)(c * CH + vv) * D + tid];
        #pragma unroll
        for (int r = 0; r < 4; r++) acc[r] += ps[r * CH + vv] * e;
    }
    #pragma unroll
    for (int r = 0; r < 4; r++)
        ypart[(size_t)c * B * D + r * D + tid] = acc[r];
}

__global__ void k_yreduce(const float* __restrict__ ypart, float* __restrict__ xd)
{
    int i = blockIdx.x * 256 + threadIdx.x;   // 0..2047
    float s = 0.f;
    #pragma unroll
    for (int c = 0; c < YCH; c++) s += ypart[(size_t)c * B * D + i];
    xd[i] = s;
}

// ---------------------------------------------------------------------------
// Host orchestration
// ---------------------------------------------------------------------------
extern "C" void kernel_launch(void* const* d_in, const int* in_sizes, int n_in,
                              void* d_out, int out_size)
{
    (void)in_sizes; (void)n_in;
    const int*   ids      = (const int*)  d_in[0];
    const float* mask     = (const float*)d_in[1];
    const float* emb      = (const float*)d_in[2];
    const float* enc_wq   = (const float*)d_in[3];
    const float* enc_wk   = (const float*)d_in[4];
    const float* enc_wv   = (const float*)d_in[5];
    const float* enc_wo   = (const float*)d_in[6];
    const float* enc_ln1  = (const float*)d_in[7];
    const float* enc_w1   = (const float*)d_in[8];
    const float* enc_w2   = (const float*)d_in[9];
    const float* enc_ln2  = (const float*)d_in[10];
    const float* enc_lnf  = (const float*)d_in[11];
    const float* dec_sq   = (const float*)d_in[12];
    const float* dec_sk   = (const float*)d_in[13];
    const float* dec_sv   = (const float*)d_in[14];
    const float* dec_so   = (const float*)d_in[15];
    const float* dec_ln1  = (const float*)d_in[16];
    const float* dec_cq   = (const float*)d_in[17];
    const float* dec_ck   = (const float*)d_in[18];
    const float* dec_cv   = (const float*)d_in[19];
    const float* dec_co   = (const float*)d_in[20];
    const float* dec_ln2  = (const float*)d_in[21];
    const float* dec_w1   = (const float*)d_in[22];
    const float* dec_w2   = (const float*)d_in[23];
    const float* dec_ln3  = (const float*)d_in[24];
    const float* dec_lnf  = (const float*)d_in[25];
    const float* lm_head  = (const float*)d_in[26];

    float* base = nullptr;
    cudaGetSymbolAddress((void**)&base, g_buf);
    float* x    = base + OFF_X;
    float* h    = base + OFF_H;
    float* q    = base + OFF_Q;
    float* k    = base + OFF_K;
    float* v    = base + OFF_V;
    float* ao   = base + OFF_AO;
    float* ff   = base + OFF_FF;
    float* hs   = base + OFF_HS;
    float* kc   = base + OFF_KC;
    float* vc   = base + OFF_VC;
    float* ksb  = base + OFF_KS;
    float* vsb  = base + OFF_VS;
    float* xd   = base + OFF_XD;
    float* qd   = base + OFF_QD;
    float* kd   = base + OFF_KD;
    float* vd   = base + OFF_VD;
    float* ad   = base + OFF_AD;
    float* ffd  = base + OFF_FFD;
    float* logits = base + OFF_LOG;
    float* yp   = base + OFF_YP;
    float* bias = base + OFF_BIAS;

    float* out = (float*)d_out;
    const size_t probs_elems = (size_t)B * T * V;
    float* flags = ((size_t)out_size >= probs_elems + (size_t)B * T)
                       ? out + probs_elems : nullptr;

    const size_t DD2 = (size_t)D * D;
    const size_t DFW = (size_t)D * DFF;

    // ---------------- Encoder ----------------
    k_embed<<<NTOK, 256>>>(ids, mask, emb, x, bias);
    for (int l = 0; l < L; l++) {
        k_rmsnorm<<<NTOK, 256>>>(x, enc_ln1 + (size_t)l * D, h);
        k_sgemm<<<dim3(D / 64, NTOK / 64, 3), 256>>>(
            h, enc_wq + l * DD2, enc_wk + l * DD2, enc_wv + l * DD2,
            nullptr, q, k, v, D, D, 0);
        k_enc_attn<<<B * H, 256>>>(q, k, v, bias, ao);
        k_sgemm<<<dim3(D / 64, NTOK / 64, 1), 256>>>(
            ao, enc_wo + l * DD2, nullptr, nullptr, x, x, nullptr, nullptr, D, D, 0);
        k_rmsnorm<<<NTOK, 256>>>(x, enc_ln2 + (size_t)l * D, h);
        k_sgemm<<<dim3(DFF / 64, NTOK / 64, 1), 256>>>(
            h, enc_w1 + l * DFW, nullptr, nullptr, nullptr, ff, nullptr, nullptr, DFF, D, 1);
        k_sgemm<<<dim3(D / 64, NTOK / 64, 1), 256>>>(
            ff, enc_w2 + l * DFW, nullptr, nullptr, x, x, nullptr, nullptr, D, DFF, 0);
    }
    k_rmsnorm<<<NTOK, 256>>>(x, enc_lnf, hs);

    // Cross-attention K/V caches (fixed across all decode steps)
    for (int l = 0; l < L; l++) {
        k_sgemm<<<dim3(D / 64, NTOK / 64, 2), 256>>>(
            hs, dec_ck + l * DD2, dec_cv + l * DD2, nullptr, nullptr,
            kc + (size_t)l * NTOK * D, vc + (size_t)l * NTOK * D, nullptr, D, D, 0);
    }

    // ---------------- Incremental decoder (mathematically identical to the
    // reference's full re-run: causal mask => prefix states never change) ----
    k_padinit<<<B, 256>>>(emb, xd);
    for (int t = 0; t < T; t++) {
        for (int l = 0; l < L; l++) {
            float* ks = ksb + (size_t)l * B * T * D;
            float* vs = vsb + (size_t)l * B * T * D;
            // self-attn QKV (fused RMSNorm ln1)
            k_vgemm<<<dim3(D / 128, 3), 128>>>(
                xd, dec_ln1 + (size_t)l * D,
                dec_sq + l * DD2, dec_sk + l * DD2, dec_sv + l * DD2,
                nullptr, qd, kd, vd, D, D, 0);
            k_dec_self<<<B * H, 64>>>(qd, kd, vd, ks, vs, ad, t);
            k_vgemm<<<dim3(D / 128, 1), 128>>>(
                ad, nullptr, dec_so + l * DD2, nullptr, nullptr,
                xd, xd, nullptr, nullptr, D, D, 0);
            // cross-attn (fused RMSNorm ln2 on q projection)
            k_vgemm<<<dim3(D / 128, 1), 128>>>(
                xd, dec_ln2 + (size_t)l * D, dec_cq + l * DD2, nullptr, nullptr,
                nullptr, qd, nullptr, nullptr, D, D, 0);
            k_dec_cross<<<B * H, 64>>>(
                qd, kc + (size_t)l * NTOK * D, vc + (size_t)l * NTOK * D, bias, ad);
            k_vgemm<<<dim3(D / 128, 1), 128>>>(
                ad, nullptr, dec_co + l * DD2, nullptr, nullptr,
                xd, xd, nullptr, nullptr, D, D, 0);
            // FFN (fused RMSNorm ln3 + relu)
            k_vgemm<<<dim3(DFF / 128, 1), 128>>>(
                xd, dec_ln3 + (size_t)l * D, dec_w1 + l * DFW, nullptr, nullptr,
                nullptr, ffd, nullptr, nullptr, D, DFF, 1);
            k_vgemm<<<dim3(D / 128, 1), 128>>>(
                ffd, nullptr, dec_w2 + l * DFW, nullptr, nullptr,
                xd, xd, nullptr, nullptr, DFF, D, 0);
        }
        k_lmhead<<<V / 128, 128>>>(xd, dec_lnf, lm_head, logits);
        k_softmax<<<B, 256>>>(logits, out, flags, t);
        // next input embedding: probs @ emb (deterministic chunked reduction)
        k_softemb<<<YCH, 512>>>(out, emb, yp, t);
        k_yreduce<<<(B * D) / 256, 256>>>(yp, xd);
    }
}

// round 7
// speedup vs baseline: 6.1246x; 6.1246x over previous
#include <cuda_runtime.h>
#include <math.h>
#include <stdint.h>

// ---------------------------------------------------------------------------
// Problem constants
// ---------------------------------------------------------------------------
namespace cfg {
constexpr int B = 4, S = 64, D = 512, H = 8, DH = 64, DFF = 2048, L = 2;
constexpr int V = 32128, T = 16;
constexpr int NTOK = B * S;
constexpr float NEG = -1e9f;
constexpr float EPS = 1e-6f;
constexpr float SCALE = 0.125f;
}
using namespace cfg;

// persistent decoder config
constexpr int NB = 128;      // co-resident blocks (<=148 SMs, 1 block/SM)
constexpr int NT = 256;
constexpr int SMF = 9216;    // floats of shared scratch (4*2048 + 256*4)

// ---------------------------------------------------------------------------
// Scratch offsets (floats)
// ---------------------------------------------------------------------------
constexpr size_t OFF_X    = 0;
constexpr size_t OFF_H    = OFF_X   + (size_t)NTOK * D;
constexpr size_t OFF_Q    = OFF_H   + (size_t)NTOK * D;
constexpr size_t OFF_K    = OFF_Q   + (size_t)NTOK * D;
constexpr size_t OFF_V    = OFF_K   + (size_t)NTOK * D;
constexpr size_t OFF_AO   = OFF_V   + (size_t)NTOK * D;
constexpr size_t OFF_FF   = OFF_AO  + (size_t)NTOK * D;
constexpr size_t OFF_HS   = OFF_FF  + (size_t)NTOK * DFF;
constexpr size_t OFF_KC   = OFF_HS  + (size_t)NTOK * D;        // cross K cache [L][NTOK][D]
constexpr size_t OFF_VC   = OFF_KC  + (size_t)L * NTOK * D;
constexpr size_t OFF_KS   = OFF_VC  + (size_t)L * NTOK * D;    // self K cache [L][B][T][D]
constexpr size_t OFF_VS   = OFF_KS  + (size_t)L * B * T * D;
constexpr size_t OFF_XD   = OFF_VS  + (size_t)L * B * T * D;   // decoder x [4][512]
constexpr size_t OFF_QD   = OFF_XD  + (size_t)B * D;
constexpr size_t OFF_KD   = OFF_QD  + (size_t)B * D;
constexpr size_t OFF_VD   = OFF_KD  + (size_t)B * D;
constexpr size_t OFF_AD   = OFF_VD  + (size_t)B * D;
constexpr size_t OFF_FFD  = OFF_AD  + (size_t)B * D;           // [4][2048]
constexpr size_t OFF_LOG  = OFF_FFD + (size_t)B * DFF;         // [4][V]
constexpr size_t OFF_BIAS = OFF_LOG + (size_t)B * V;           // [B*S]
constexpr size_t OFF_H4   = OFF_BIAS + (size_t)B * S;          // normed x [4][512]
constexpr size_t OFF_TMP  = OFF_H4  + (size_t)B * D;           // pending residual [4][512]
constexpr size_t OFF_PM   = OFF_TMP + (size_t)B * D;           // softmax seg max [128]
constexpr size_t OFF_PI   = OFF_PM  + 128;                     // seg argmax [128] (int)
constexpr size_t OFF_PS   = OFF_PI  + 128;                     // seg expsum [128]
constexpr size_t OFF_GM   = OFF_PS  + 128;                     // [4]
constexpr size_t OFF_GI   = OFF_GM  + 4;                       // [4] inv-sum
constexpr size_t OFF_PSEM = OFF_GI  + 4;                       // softemb partials [64][4][512]
constexpr size_t TOTALF   = OFF_PSEM + (size_t)64 * 4 * 512;

__device__ __align__(16) float g_buf[TOTALF];
__device__ unsigned g_cnt;
__device__ unsigned g_gen;

// ---------------------------------------------------------------------------
// Software grid barrier (all NB blocks co-resident)
// ---------------------------------------------------------------------------
__device__ __forceinline__ void gsync()
{
    __syncthreads();
    if (threadIdx.x == 0) {
        unsigned gen = *(volatile unsigned*)&g_gen;
        __threadfence();
        if (atomicAdd(&g_cnt, 1u) == NB - 1) {
            *(volatile unsigned*)&g_cnt = 0u;
            __threadfence();
            *(volatile unsigned*)&g_gen = gen + 1u;
        } else {
            while (*(volatile unsigned*)&g_gen == gen) { }
        }
        __threadfence();
    }
    __syncthreads();
}

// ---------------------------------------------------------------------------
// Encoder kernels (multi-launch; ~15 nodes total)
// ---------------------------------------------------------------------------
__global__ void k_embed(const int* __restrict__ ids, const float* __restrict__ mask,
                        const float* __restrict__ emb, float* __restrict__ x,
                        float* __restrict__ bias)
{
    int tok = blockIdx.x, tid = threadIdx.x;
    int id = ids[tok];
    const float* e = emb + (size_t)id * D;
    x[(size_t)tok * D + tid]       = e[tid];
    x[(size_t)tok * D + 256 + tid] = e[256 + tid];
    if (tid == 0) bias[tok] = (1.0f - mask[tok]) * NEG;
}

__global__ void k_padinit(const float* __restrict__ emb, float* __restrict__ xd)
{
    int b = blockIdx.x, tid = threadIdx.x;
    xd[(size_t)b * D + tid]       = emb[tid];
    xd[(size_t)b * D + 256 + tid] = emb[256 + tid];
}

__global__ void k_rmsnorm(const float* __restrict__ x, const float* __restrict__ w,
                          float* __restrict__ y)
{
    int r = blockIdx.x, tid = threadIdx.x;
    __shared__ float red[256];
    float v0 = x[(size_t)r * D + tid];
    float v1 = x[(size_t)r * D + 256 + tid];
    red[tid] = v0 * v0 + v1 * v1;
    __syncthreads();
    for (int s = 128; s > 0; s >>= 1) {
        if (tid < s) red[tid] += red[tid + s];
        __syncthreads();
    }
    float sc = rsqrtf(red[0] * (1.0f / D) + EPS);
    y[(size_t)r * D + tid]       = v0 * sc * w[tid];
    y[(size_t)r * D + 256 + tid] = v1 * sc * w[256 + tid];
}

__global__ void k_sgemm(const float* __restrict__ A,
                        const float* __restrict__ W0, const float* __restrict__ W1,
                        const float* __restrict__ W2,
                        const float* __restrict__ Res,
                        float* __restrict__ C0, float* __restrict__ C1, float* __restrict__ C2,
                        int N, int K, int relu)
{
    const float* W = (blockIdx.z == 0) ? W0 : (blockIdx.z == 1) ? W1 : W2;
    float* C       = (blockIdx.z == 0) ? C0 : (blockIdx.z == 1) ? C1 : C2;
    __shared__ float As[64 * 16];
    __shared__ float Bs[16 * 64];
    int tid = threadIdx.x;
    int tx = tid & 15, ty = tid >> 4;
    int bm = blockIdx.y * 64, bn = blockIdx.x * 64;
    float acc[4][4] = {};
    for (int k0 = 0; k0 < K; k0 += 16) {
        {
            int r = tid >> 2, c = (tid & 3) << 2;
            *(float4*)&As[r * 16 + c] = *(const float4*)&A[(size_t)(bm + r) * K + k0 + c];
        }
        {
            int r = tid >> 4, c = (tid & 15) << 2;
            *(float4*)&Bs[r * 64 + c] = *(const float4*)&W[(size_t)(k0 + r) * N + bn + c];
        }
        __syncthreads();
        #pragma unroll
        for (int k = 0; k < 16; k++) {
            float am[4], bv[4];
            #pragma unroll
            for (int i = 0; i < 4; i++) am[i] = As[(ty * 4 + i) * 16 + k];
            #pragma unroll
            for (int j = 0; j < 4; j++) bv[j] = Bs[k * 64 + tx * 4 + j];
            #pragma unroll
            for (int i = 0; i < 4; i++)
                #pragma unroll
                for (int j = 0; j < 4; j++) acc[i][j] += am[i] * bv[j];
        }
        __syncthreads();
    }
    #pragma unroll
    for (int i = 0; i < 4; i++) {
        int row = bm + ty * 4 + i;
        #pragma unroll
        for (int j = 0; j < 4; j++) {
            int col = bn + tx * 4 + j;
            float v = acc[i][j];
            if (Res) v += Res[(size_t)row * N + col];
            if (relu) v = fmaxf(v, 0.0f);
            C[(size_t)row * N + col] = v;
        }
    }
}

// Encoder self-attention, q-dimension split 4-way: grid (B*H, 4), 256 threads.
__global__ void k_enc_attn(const float* __restrict__ q, const float* __restrict__ k,
                           const float* __restrict__ v, const float* __restrict__ bias,
                           float* __restrict__ out)
{
    int bh = blockIdx.x, b = bh >> 3, h = bh & 7;
    int q0 = blockIdx.y * 16;
    int tid = threadIdx.x;
    __shared__ float sc[16 * 64];
    for (int i = tid; i < 1024; i += 256) {
        int qi = q0 + (i >> 6), ki = i & 63;
        const float* qp = &q[(size_t)(b * S + qi) * D + h * DH];
        const float* kp = &k[(size_t)(b * S + ki) * D + h * DH];
        float s = 0.f;
        #pragma unroll 16
        for (int e = 0; e < DH; e++) s += qp[e] * kp[e];
        sc[i] = s * SCALE + bias[b * S + ki];
    }
    __syncthreads();
    if (tid < 16) {
        float* row = &sc[tid * 64];
        float m = -1e30f;
        for (int j = 0; j < 64; j++) m = fmaxf(m, row[j]);
        float ss = 0.f;
        for (int j = 0; j < 64; j++) { row[j] = __expf(row[j] - m); ss += row[j]; }
        float inv = 1.0f / ss;
        for (int j = 0; j < 64; j++) row[j] *= inv;
    }
    __syncthreads();
    for (int i = tid; i < 1024; i += 256) {
        int qr = i >> 6, dd = i & 63;
        float o = 0.f;
        #pragma unroll 16
        for (int j = 0; j < 64; j++)
            o += sc[qr * 64 + j] * v[(size_t)(b * S + j) * D + h * DH + dd];
        out[(size_t)(b * S + q0 + qr) * D + h * DH + dd] = o;
    }
}

// ---------------------------------------------------------------------------
// Persistent decoder: device stage helpers
// ---------------------------------------------------------------------------

// RMSNorm on 4 rows (blocks 0..3), optional "pending residual" add into xd.
__device__ __forceinline__ void stage_norm(float* sm, float* xd, const float* tmp,
                                           const float* LN, float* h4, int addres)
{
    if (blockIdx.x < 4) {
        int r = blockIdx.x, tid = threadIdx.x;
        float x0 = xd[r * D + tid];
        float x1 = xd[r * D + 256 + tid];
        if (addres) {
            x0 += tmp[r * D + tid];
            x1 += tmp[r * D + 256 + tid];
            xd[r * D + tid] = x0;
            xd[r * D + 256 + tid] = x1;
        }
        sm[tid] = x0 * x0 + x1 * x1;
        __syncthreads();
        for (int s = 128; s > 0; s >>= 1) {
            if (tid < s) sm[tid] += sm[tid + s];
            __syncthreads();
        }
        float sc = rsqrtf(sm[0] * (1.0f / D) + EPS);
        h4[r * D + tid]       = x0 * sc * LN[tid];
        h4[r * D + 256 + tid] = x1 * sc * LN[256 + tid];
    }
    gsync();
}

// Block-internal split-K GEMM: C[4][N] = A[4][K] @ W[K][N]. One block computes
// NLB output columns with NT/NLB k-groups reduced through shared memory.
template<int K, int N, int NLB, int RELU>
__device__ __forceinline__ void gemm_block(float* sm, const float* __restrict__ A4,
                                           const float* __restrict__ W,
                                           float* __restrict__ C, int nc)
{
    constexpr int KG = NT / NLB;
    constexpr int KPT = K / KG;
    int tid = threadIdx.x;
    int nl = tid % NLB, kg = tid / NLB;
    int n = nc * NLB + nl;
    float* a_sh = sm;
    for (int i = tid; i < 4 * K; i += NT) a_sh[i] = A4[i];
    __syncthreads();
    float a0 = 0.f, a1 = 0.f, a2 = 0.f, a3 = 0.f;
    int kb = kg * KPT;
    const float* Wp = W + (size_t)kb * N + n;
    #pragma unroll 16
    for (int kk = 0; kk < KPT; kk++) {
        float w = Wp[(size_t)kk * N];
        int k = kb + kk;
        a0 += a_sh[k] * w;
        a1 += a_sh[K + k] * w;
        a2 += a_sh[2 * K + k] * w;
        a3 += a_sh[3 * K + k] * w;
    }
    float* red = sm + 4 * K;
    red[tid] = a0; red[NT + tid] = a1; red[2 * NT + tid] = a2; red[3 * NT + tid] = a3;
    __syncthreads();
    if (kg == 0) {
        #pragma unroll
        for (int r = 0; r < 4; r++) {
            float s2 = 0.f;
            #pragma unroll 8
            for (int g = 0; g < KG; g++) s2 += red[r * NT + g * NLB + nl];
            if (RELU) s2 = fmaxf(s2, 0.0f);
            C[(size_t)r * N + n] = s2;
        }
    }
}

struct DecArgs {
    const float *emb, *sq, *sk, *sv, *so, *ln1, *cq, *co, *ln2;
    const float *w1, *w2, *ln3, *lnf, *lm;
    float *out, *flags;
};

__global__ __launch_bounds__(NT, 1) void k_decoder(DecArgs a)
{
    __shared__ float sm[SMF];
    const int bid = blockIdx.x, tid = threadIdx.x;

    float* xd   = g_buf + OFF_XD;
    float* qd   = g_buf + OFF_QD;
    float* kd   = g_buf + OFF_KD;
    float* vd   = g_buf + OFF_VD;
    float* ad   = g_buf + OFF_AD;
    float* ffd  = g_buf + OFF_FFD;
    float* logits = g_buf + OFF_LOG;
    float* bias = g_buf + OFF_BIAS;
    float* h4   = g_buf + OFF_H4;
    float* tmp  = g_buf + OFF_TMP;
    float* PM   = g_buf + OFF_PM;
    int*   PI   = (int*)(g_buf + OFF_PI);
    float* PS   = g_buf + OFF_PS;
    float* GM   = g_buf + OFF_GM;
    float* GI   = g_buf + OFF_GI;
    float* PSEM = g_buf + OFF_PSEM;
    float* kcc  = g_buf + OFF_KC;
    float* vcc  = g_buf + OFF_VC;
    float* ksb  = g_buf + OFF_KS;
    float* vsb  = g_buf + OFF_VS;

    const size_t DD2 = (size_t)D * D;
    const size_t DFW = (size_t)D * DFF;

    for (int t = 0; t < T; t++) {
        for (int l = 0; l < L; l++) {
            const float* SQ = a.sq + l * DD2;
            const float* SK = a.sk + l * DD2;
            const float* SV = a.sv + l * DD2;
            const float* SO = a.so + l * DD2;
            const float* CQ = a.cq + l * DD2;
            const float* CO = a.co + l * DD2;
            const float* W1 = a.w1 + l * DFW;
            const float* W2 = a.w2 + l * DFW;
            float* ks = ksb + (size_t)l * B * T * D;
            float* vs = vsb + (size_t)l * B * T * D;
            const float* kc = kcc + (size_t)l * NTOK * D;
            const float* vc = vcc + (size_t)l * NTOK * D;

            // norm1 (+ pending residual from previous layer's w2)
            stage_norm(sm, xd, tmp, a.ln1 + (size_t)l * D, h4, l > 0);

            // QKV projections: 96 blocks, 32 n-chunks of 16 per matrix
            if (bid < 96) {
                int mat = bid >> 5, nc = bid & 31;
                const float* W = (mat == 0) ? SQ : (mat == 1) ? SK : SV;
                float* C = (mat == 0) ? qd : (mat == 1) ? kd : vd;
                gemm_block<512, 512, 16, 0>(sm, h4, W, C, nc);
            }
            gsync();

            // self-attention over cache 0..t (blocks = (b,h))
            if (bid < 32) {
                int b = bid >> 3, h = bid & 7;
                float* qs = sm;
                float* at = sm + 64;
                if (tid < 64) {
                    int base = b * D + h * DH + tid;
                    ks[(size_t)(b * T + t) * D + h * DH + tid] = kd[base];
                    vs[(size_t)(b * T + t) * D + h * DH + tid] = vd[base];
                    qs[tid] = qd[base];
                }
                __syncthreads();
                if (tid < 64 && tid <= t) {
                    const float* kp = &ks[(size_t)(b * T + tid) * D + h * DH];
                    float s = 0.f;
                    #pragma unroll 16
                    for (int e = 0; e < DH; e++) s += qs[e] * kp[e];
                    at[tid] = s * SCALE;
                }
                __syncthreads();
                if (tid == 0) {
                    float m = -1e30f;
                    for (int j = 0; j <= t; j++) m = fmaxf(m, at[j]);
                    float ss = 0.f;
                    for (int j = 0; j <= t; j++) { at[j] = __expf(at[j] - m); ss += at[j]; }
                    float inv = 1.0f / ss;
                    for (int j = 0; j <= t; j++) at[j] *= inv;
                }
                __syncthreads();
                if (tid < 64) {
                    float o = 0.f;
                    for (int j = 0; j <= t; j++)
                        o += at[j] * vs[(size_t)(b * T + j) * D + h * DH + tid];
                    ad[b * D + h * DH + tid] = o;
                }
            }
            gsync();

            // self out-projection -> tmp (residual folded into norm2)
            if (bid < 64) gemm_block<512, 512, 8, 0>(sm, ad, SO, tmp, bid);
            gsync();

            stage_norm(sm, xd, tmp, a.ln2 + (size_t)l * D, h4, 1);

            // cross q projection
            if (bid < 64) gemm_block<512, 512, 8, 0>(sm, h4, CQ, qd, bid);
            gsync();

            // cross-attention over 64 cached encoder keys
            if (bid < 32) {
                int b = bid >> 3, h = bid & 7;
                float* qs = sm;
                float* at = sm + 64;
                if (tid < 64) qs[tid] = qd[b * D + h * DH + tid];
                __syncthreads();
                if (tid < 64) {
                    const float* kp = &kc[(size_t)(b * S + tid) * D + h * DH];
                    float s = 0.f;
                    #pragma unroll 16
                    for (int e = 0; e < DH; e++) s += qs[e] * kp[e];
                    at[tid] = s * SCALE + bias[b * S + tid];
                }
                __syncthreads();
                if (tid == 0) {
                    float m = -1e30f;
                    for (int j = 0; j < S; j++) m = fmaxf(m, at[j]);
                    float ss = 0.f;
                    for (int j = 0; j < S; j++) { at[j] = __expf(at[j] - m); ss += at[j]; }
                    float inv = 1.0f / ss;
                    for (int j = 0; j < S; j++) at[j] *= inv;
                }
                __syncthreads();
                if (tid < 64) {
                    float o = 0.f;
                    #pragma unroll 8
                    for (int j = 0; j < S; j++)
                        o += at[j] * vc[(size_t)(b * S + j) * D + h * DH + tid];
                    ad[b * D + h * DH + tid] = o;
                }
            }
            gsync();

            if (bid < 64) gemm_block<512, 512, 8, 0>(sm, ad, CO, tmp, bid);
            gsync();

            stage_norm(sm, xd, tmp, a.ln3 + (size_t)l * D, h4, 1);

            // FFN
            if (bid < 128) gemm_block<512, 2048, 16, 1>(sm, h4, W1, ffd, bid);
            gsync();
            if (bid < 64) gemm_block<2048, 512, 8, 0>(sm, ffd, W2, tmp, bid);
            gsync();
        }

        // final norm (+w2 residual)
        stage_norm(sm, xd, tmp, a.lnf, h4, 1);

        // lm_head: 1 thread per vocab column, all 128 blocks
        {
            for (int i = tid; i < 4 * D; i += NT) sm[i] = h4[i];
            __syncthreads();
            int n = bid * NT + tid;
            if (n < V) {
                float a0 = 0.f, a1 = 0.f, a2 = 0.f, a3 = 0.f;
                const float* Wp = a.lm + n;
                #pragma unroll 16
                for (int k = 0; k < D; k++) {
                    float w = Wp[(size_t)k * V];
                    a0 += sm[k] * w;
                    a1 += sm[D + k] * w;
                    a2 += sm[2 * D + k] * w;
                    a3 += sm[3 * D + k] * w;
                }
                logits[n] = a0;
                logits[(size_t)V + n] = a1;
                logits[(size_t)2 * V + n] = a2;
                logits[(size_t)3 * V + n] = a3;
            }
        }
        gsync();

        // softmax P1: per-(row,segment) local max/argmax/expsum (32 segs of 1004)
        {
            int r = bid >> 5, seg = bid & 31;
            int v0 = seg * 1004;
            const float* lg = logits + (size_t)r * V;
            float m = -1e30f; int mi = v0;
            for (int vv = tid; vv < 1004; vv += NT) {
                float x = lg[v0 + vv];
                if (x > m) { m = x; mi = v0 + vv; }
            }
            float* smv = sm;
            int* smi = (int*)(sm + NT);
            smv[tid] = m; smi[tid] = mi;
            __syncthreads();
            for (int s = 128; s > 0; s >>= 1) {
                if (tid < s) {
                    if (smv[tid + s] > smv[tid] ||
                        (smv[tid + s] == smv[tid] && smi[tid + s] < smi[tid])) {
                        smv[tid] = smv[tid + s];
                        smi[tid] = smi[tid + s];
                    }
                }
                __syncthreads();
            }
            float bm = smv[0]; int bmi = smi[0];
            __syncthreads();
            float es = 0.f;
            for (int vv = tid; vv < 1004; vv += NT) es += __expf(lg[v0 + vv] - bm);
            smv[tid] = es;
            __syncthreads();
            for (int s = 128; s > 0; s >>= 1) {
                if (tid < s) smv[tid] += smv[tid + s];
                __syncthreads();
            }
            if (tid == 0) { PM[bid] = bm; PI[bid] = bmi; PS[bid] = smv[0]; }
        }
        gsync();

        // softmax P2: combine 32 segments per row, write pred flag
        if (bid < 4 && tid == 0) {
            int r = bid;
            float gm = -1e30f; int gi = 0;
            for (int s2 = 0; s2 < 32; s2++) {
                float m2 = PM[r * 32 + s2];
                if (m2 > gm) { gm = m2; gi = PI[r * 32 + s2]; }
            }
            float gs = 0.f;
            for (int s2 = 0; s2 < 32; s2++)
                gs += PS[r * 32 + s2] * __expf(PM[r * 32 + s2] - gm);
            GM[r] = gm;
            GI[r] = 1.0f / gs;
            if (a.flags) a.flags[r * T + t] = (gi == 0) ? 1.0f : 0.0f;  // PAD_ID==0
        }
        gsync();

        // P3: write probs + softemb partials (probs @ emb), split-K over 64 v-chunks
        {
            int nc = bid & 1, ks2 = bid >> 1;
            int v0 = ks2 * 502;                      // 64*502 == 32128
            float* p_sh = sm;                        // [4][502]
            for (int i = tid; i < 4 * 502; i += NT) {
                int r = i / 502, vv = i - r * 502;
                int v = v0 + vv;
                float p = __expf(logits[(size_t)r * V + v] - GM[r]) * GI[r];
                p_sh[i] = p;
                if (nc == 0) a.out[((size_t)r * T + t) * V + v] = p;
            }
            __syncthreads();
            int n = nc * 256 + tid;
            float a0 = 0.f, a1 = 0.f, a2 = 0.f, a3 = 0.f;
            const float* ep = a.emb + (size_t)v0 * D + n;
            #pragma unroll 8
            for (int vv = 0; vv < 502; vv++) {
                float e = ep[(size_t)vv * D];
                a0 += p_sh[vv] * e;
                a1 += p_sh[502 + vv] * e;
                a2 += p_sh[1004 + vv] * e;
                a3 += p_sh[1506 + vv] * e;
            }
            PSEM[((size_t)ks2 * 4 + 0) * D + n] = a0;
            PSEM[((size_t)ks2 * 4 + 1) * D + n] = a1;
            PSEM[((size_t)ks2 * 4 + 2) * D + n] = a2;
            PSEM[((size_t)ks2 * 4 + 3) * D + n] = a3;
        }
        gsync();

        // P4: reduce softemb partials -> next xd (fixed order, deterministic)
        {
            int gid = bid * NT + tid;
            if (gid < 4 * D) {
                int r = gid >> 9, n = gid & 511;
                float s = 0.f;
                #pragma unroll 8
                for (int ksx = 0; ksx < 64; ksx++)
                    s += PSEM[((size_t)ksx * 4 + r) * D + n];
                xd[gid] = s;
            }
        }
        gsync();
    }
}

// ---------------------------------------------------------------------------
// Host orchestration
// ---------------------------------------------------------------------------
extern "C" void kernel_launch(void* const* d_in, const int* in_sizes, int n_in,
                              void* d_out, int out_size)
{
    (void)in_sizes; (void)n_in;
    const int*   ids      = (const int*)  d_in[0];
    const float* mask     = (const float*)d_in[1];
    const float* emb      = (const float*)d_in[2];
    const float* enc_wq   = (const float*)d_in[3];
    const float* enc_wk   = (const float*)d_in[4];
    const float* enc_wv   = (const float*)d_in[5];
    const float* enc_wo   = (const float*)d_in[6];
    const float* enc_ln1  = (const float*)d_in[7];
    const float* enc_w1   = (const float*)d_in[8];
    const float* enc_w2   = (const float*)d_in[9];
    const float* enc_ln2  = (const float*)d_in[10];
    const float* enc_lnf  = (const float*)d_in[11];
    const float* dec_sq   = (const float*)d_in[12];
    const float* dec_sk   = (const float*)d_in[13];
    const float* dec_sv   = (const float*)d_in[14];
    const float* dec_so   = (const float*)d_in[15];
    const float* dec_ln1  = (const float*)d_in[16];
    const float* dec_cq   = (const float*)d_in[17];
    const float* dec_ck   = (const float*)d_in[18];
    const float* dec_cv   = (const float*)d_in[19];
    const float* dec_co   = (const float*)d_in[20];
    const float* dec_ln2  = (const float*)d_in[21];
    const float* dec_w1   = (const float*)d_in[22];
    const float* dec_w2   = (const float*)d_in[23];
    const float* dec_ln3  = (const float*)d_in[24];
    const float* dec_lnf  = (const float*)d_in[25];
    const float* lm_head  = (const float*)d_in[26];

    float* base = nullptr;
    cudaGetSymbolAddress((void**)&base, g_buf);
    float* x    = base + OFF_X;
    float* h    = base + OFF_H;
    float* q    = base + OFF_Q;
    float* k    = base + OFF_K;
    float* v    = base + OFF_V;
    float* ao   = base + OFF_AO;
    float* ff   = base + OFF_FF;
    float* hs   = base + OFF_HS;
    float* kc   = base + OFF_KC;
    float* vc   = base + OFF_VC;
    float* xd   = base + OFF_XD;
    float* bias = base + OFF_BIAS;

    float* out = (float*)d_out;
    const size_t probs_elems = (size_t)B * T * V;
    float* flags = ((size_t)out_size >= probs_elems + (size_t)B * T)
                       ? out + probs_elems : nullptr;

    const size_t DD2 = (size_t)D * D;
    const size_t DFW = (size_t)D * DFF;

    // ---------------- Encoder ----------------
    k_embed<<<NTOK, 256>>>(ids, mask, emb, x, bias);
    for (int l = 0; l < L; l++) {
        k_rmsnorm<<<NTOK, 256>>>(x, enc_ln1 + (size_t)l * D, h);
        k_sgemm<<<dim3(D / 64, NTOK / 64, 3), 256>>>(
            h, enc_wq + l * DD2, enc_wk + l * DD2, enc_wv + l * DD2,
            nullptr, q, k, v, D, D, 0);
        k_enc_attn<<<dim3(B * H, 4), 256>>>(q, k, v, bias, ao);
        k_sgemm<<<dim3(D / 64, NTOK / 64, 1), 256>>>(
            ao, enc_wo + l * DD2, nullptr, nullptr, x, x, nullptr, nullptr, D, D, 0);
        k_rmsnorm<<<NTOK, 256>>>(x, enc_ln2 + (size_t)l * D, h);
        k_sgemm<<<dim3(DFF / 64, NTOK / 64, 1), 256>>>(
            h, enc_w1 + l * DFW, nullptr, nullptr, nullptr, ff, nullptr, nullptr, DFF, D, 1);
        k_sgemm<<<dim3(D / 64, NTOK / 64, 1), 256>>>(
            ff, enc_w2 + l * DFW, nullptr, nullptr, x, x, nullptr, nullptr, D, DFF, 0);
    }
    k_rmsnorm<<<NTOK, 256>>>(x, enc_lnf, hs);

    // cross-attention K/V caches (fixed over decode)
    for (int l = 0; l < L; l++) {
        k_sgemm<<<dim3(D / 64, NTOK / 64, 2), 256>>>(
            hs, dec_ck + l * DD2, dec_cv + l * DD2, nullptr, nullptr,
            kc + (size_t)l * NTOK * D, vc + (size_t)l * NTOK * D, nullptr, D, D, 0);
    }

    // ---------------- Persistent incremental decoder ----------------
    k_padinit<<<B, 256>>>(emb, xd);
    DecArgs da;
    da.emb = emb;
    da.sq = dec_sq; da.sk = dec_sk; da.sv = dec_sv; da.so = dec_so; da.ln1 = dec_ln1;
    da.cq = dec_cq; da.co = dec_co; da.ln2 = dec_ln2;
    da.w1 = dec_w1; da.w2 = dec_w2; da.ln3 = dec_ln3;
    da.lnf = dec_lnf; da.lm = lm_head;
    da.out = out; da.flags = flags;
    k_decoder<<<NB, NT>>>(da);
}